// round 14
// baseline (speedup 1.0000x reference)
#include <cuda_runtime.h>
#include <cuda_bf16.h>
#include <math.h>

#define T_  128
#define B_  32
#define D_  512
#define H_  512
#define N_  64
#define A_  32
#define G3_ 1536
#define NB_ 128

// smem layout (floats) for k_step
#define SW_HM  0
#define SW_BOT 2048
#define SW_TOP 4096
#define SW_UM  6144
#define SW_R   6400
#define SW_Z   8448
#define SW_N   10496
#define SM_RED 12544
#define SMEM_FLOATS (SM_RED + 16*384)
#define SMEM_BYTES  (SMEM_FLOATS * 4)

typedef unsigned long long u64;

// ---------------- device scratch ----------------
__device__ float g_xT  [(size_t)T_*D_*B_];    // [t][k][b]
__device__ float g_wiT [(size_t)T_*G3_*B_];   // x@W_ih + bias_ih, [t][j][b]
__device__ float g_xmT [(size_t)T_*H_*B_];    // x@W_im, [t][m][b]
__device__ float g_gum [(size_t)T_*B_*N_];    // gumbel + fc1_b, [t][b][n]
__device__ float g_hsT [(size_t)T_*H_*B_];    // hs outputs [t][m][b]
__device__ float g_hT     [H_*B_];            // h, [m][b]
__device__ float g_pre    [H_*B_];            // tanh preact, [m][b]
__device__ float g_accbot [B_*H_];            // h@fc2_w[H:], [b][m]
__device__ float g_hnewT  [H_*B_];            // [m][b]
__device__ float g_MF  [(size_t)B_*N_*H_];    // MF[b][n][m] = mem[b,n]@fc2_w[:H]
__device__ float g_usage[B_*N_];
__device__ float g_lu   [N_*B_];              // sigmoid(usage), [n][b]
__device__ int   g_hard [B_];
__device__ unsigned g_cnt;                    // arrival counter (block0-only poller)
__device__ unsigned g_rel[8*32];              // 8 release words, 128B apart

// ---------------- f32x2 packed helpers ----------------
__device__ __forceinline__ u64 fma2(u64 a, u64 b, u64 c) {
    u64 d;
    asm("fma.rn.f32x2 %0, %1, %2, %3;" : "=l"(d) : "l"(a), "l"(b), "l"(c));
    return d;
}
__device__ __forceinline__ u64 pack2(float x) {
    u64 d;
    unsigned xi = __float_as_uint(x);
    asm("mov.b64 %0, {%1, %1};" : "=l"(d) : "r"(xi));
    return d;
}
__device__ __forceinline__ float2 unpack2(u64 v) {
    float2 f;
    asm("mov.b64 {%0, %1}, %2;" : "=f"(f.x), "=f"(f.y) : "l"(v));
    return f;
}

// ---------------- accurate fp32 log (immune to --use_fast_math) ----------
__device__ __forceinline__ float acc_logf(float x) {
    int e;
    float m = frexpf(x, &e);                 // m in [0.5,1)
    if (m < 0.70710678f) { m = m + m; e -= 1; }
    float s = (m - 1.0f) / (m + 1.0f);       // |s| <= 0.1716
    float s2 = s * s;
    float p = 2.0f/9.0f;
    p = fmaf(p, s2, 2.0f/7.0f);
    p = fmaf(p, s2, 2.0f/5.0f);
    p = fmaf(p, s2, 2.0f/3.0f);
    p = fmaf(p, s2, 2.0f);
    return fmaf((float)e, 0.6931471805599453f, s * p);
}

// ---------------- grid barrier: tree release (block0 fans out) -----------
// All blocks RED the counter. ONLY block 0 polls it (1 poller: no LTS
// same-address saturation), then release-stores to 8 spread words; other
// blocks poll their word (<=16 pollers/line). Acquire-release chains compose.
__device__ __forceinline__ void grid_bar(unsigned bar) {
    __syncthreads();
    if (threadIdx.x == 0) {
        asm volatile("red.release.gpu.global.add.u32 [%0], 1;"
                     :: "l"(&g_cnt) : "memory");
        if (blockIdx.x == 0) {
            unsigned v;
            do {
                asm volatile("ld.acquire.gpu.global.u32 %0, [%1];"
                             : "=r"(v) : "l"(&g_cnt) : "memory");
            } while (v < bar * NB_);
#pragma unroll
            for (int i = 0; i < 8; i++)
                asm volatile("st.release.gpu.global.u32 [%0], %1;"
                             :: "l"(&g_rel[i*32]), "r"(bar) : "memory");
        } else {
            unsigned v;
            const unsigned* wp = &g_rel[(blockIdx.x & 7) * 32];
            do {
                asm volatile("ld.acquire.gpu.global.u32 %0, [%1];"
                             : "=r"(v) : "l"(wp) : "memory");
            } while (v < bar);
        }
    }
    __syncthreads();
}

// ---------------- init (every launch: graph-replay determinism) ----------
__global__ void k_init() {
    size_t i = (size_t)blockIdx.x * blockDim.x + threadIdx.x;
    size_t stride = (size_t)gridDim.x * blockDim.x;
    for (size_t j = i; j < (size_t)B_*N_*H_; j += stride) g_MF[j] = 0.f;
    if (i < (size_t)H_*B_) g_hT[i] = 0.f;
    if (i < (size_t)B_*N_) { g_usage[i] = -99999.f; }
    if (i < (size_t)N_*B_) { g_lu[i] = 0.f; }
    if (i < B_) g_hard[i] = 0;
    if (i == 0) g_cnt = 0u;
    if (i < 8*32) g_rel[i] = 0u;
}

// ---------------- gumbel precompute: g + fc1_b ----------------
__global__ void k_gumbel(const float* __restrict__ u_noise,
                         const float* __restrict__ fc1_b) {
    int i = blockIdx.x * blockDim.x + threadIdx.x;
    if (i >= T_*B_*N_) return;
    float u = u_noise[i];
    float l1 = acc_logf(1e-20f + u);
    float g = -acc_logf(1e-20f - l1);
    g_gum[i] = g + fc1_b[i & (N_-1)];
}

// ---------------- transpose x[t][b][k] -> g_xT[t][k][b] ----------------
__global__ void k_transpose(const float* __restrict__ x) {
    __shared__ float tile[32][33];
    int t = blockIdx.x;
    int w = threadIdx.x >> 5, lane = threadIdx.x & 31;   // 16 warps
    for (int k0 = 0; k0 < D_; k0 += 32) {
#pragma unroll
        for (int bb = 0; bb < 32; bb += 16) {
            int b = w + bb;
            tile[b][lane] = x[((size_t)(t*B_ + b))*D_ + k0 + lane];
        }
        __syncthreads();
#pragma unroll
        for (int kk = 0; kk < 32; kk += 16) {
            int k = k0 + w + kk;
            g_xT[((size_t)t*D_ + k)*B_ + lane] = tile[lane][w + kk];
        }
        __syncthreads();
    }
}

// ---------------- precompute x@W_ih (+bias_ih) and x@W_im ----------------
// 2 timesteps per block (same column group): halves weight-load issue/MAC.
// grid = (T_/2)*16 blocks of 128 threads; warp = b-octet.
__global__ void k_pregemm(const float* __restrict__ W_ih,
                          const float* __restrict__ W_im,
                          const float* __restrict__ bias) {
    const int warp = threadIdx.x >> 5, lane = threadIdx.x & 31;
    const int tp = blockIdx.x >> 4, cg = blockIdx.x & 15;
    const int t0 = tp << 1;
    const bool isIH = (cg < 12);
    const int c0 = (isIH ? cg : cg - 12) << 7;          // 128-column group base
    const int stride = isIH ? G3_ : H_;
    const float* Wp = (isIH ? W_ih : W_im) + c0 + (lane << 2);
    const float* Xa = g_xT + (size_t)t0 * D_ * B_ + (warp << 3);
    const float* Xb = Xa + (size_t)D_ * B_;

    u64 a0[4][4], a1[4][4];                              // [col j][b-pair p]
#pragma unroll
    for (int j = 0; j < 4; j++)
#pragma unroll
        for (int p = 0; p < 4; p++) { a0[j][p] = 0ull; a1[j][p] = 0ull; }

#pragma unroll 4
    for (int k = 0; k < D_; k++) {
        ulonglong2 A1 = *(const ulonglong2*)(Xa + (size_t)k*B_);
        ulonglong2 A2 = *(const ulonglong2*)(Xa + (size_t)k*B_ + 4);
        ulonglong2 Bb1 = *(const ulonglong2*)(Xb + (size_t)k*B_);
        ulonglong2 Bb2 = *(const ulonglong2*)(Xb + (size_t)k*B_ + 4);
        float4 wv = *(const float4*)(Wp + (size_t)k*stride);
        u64 w0 = pack2(wv.x), w1 = pack2(wv.y), w2 = pack2(wv.z), w3 = pack2(wv.w);
        a0[0][0]=fma2(A1.x,w0,a0[0][0]); a0[0][1]=fma2(A1.y,w0,a0[0][1]);
        a0[0][2]=fma2(A2.x,w0,a0[0][2]); a0[0][3]=fma2(A2.y,w0,a0[0][3]);
        a0[1][0]=fma2(A1.x,w1,a0[1][0]); a0[1][1]=fma2(A1.y,w1,a0[1][1]);
        a0[1][2]=fma2(A2.x,w1,a0[1][2]); a0[1][3]=fma2(A2.y,w1,a0[1][3]);
        a0[2][0]=fma2(A1.x,w2,a0[2][0]); a0[2][1]=fma2(A1.y,w2,a0[2][1]);
        a0[2][2]=fma2(A2.x,w2,a0[2][2]); a0[2][3]=fma2(A2.y,w2,a0[2][3]);
        a0[3][0]=fma2(A1.x,w3,a0[3][0]); a0[3][1]=fma2(A1.y,w3,a0[3][1]);
        a0[3][2]=fma2(A2.x,w3,a0[3][2]); a0[3][3]=fma2(A2.y,w3,a0[3][3]);
        a1[0][0]=fma2(Bb1.x,w0,a1[0][0]); a1[0][1]=fma2(Bb1.y,w0,a1[0][1]);
        a1[0][2]=fma2(Bb2.x,w0,a1[0][2]); a1[0][3]=fma2(Bb2.y,w0,a1[0][3]);
        a1[1][0]=fma2(Bb1.x,w1,a1[1][0]); a1[1][1]=fma2(Bb1.y,w1,a1[1][1]);
        a1[1][2]=fma2(Bb2.x,w1,a1[1][2]); a1[1][3]=fma2(Bb2.y,w1,a1[1][3]);
        a1[2][0]=fma2(Bb1.x,w2,a1[2][0]); a1[2][1]=fma2(Bb1.y,w2,a1[2][1]);
        a1[2][2]=fma2(Bb2.x,w2,a1[2][2]); a1[2][3]=fma2(Bb2.y,w2,a1[2][3]);
        a1[3][0]=fma2(Bb1.x,w3,a1[3][0]); a1[3][1]=fma2(Bb1.y,w3,a1[3][1]);
        a1[3][2]=fma2(Bb2.x,w3,a1[3][2]); a1[3][3]=fma2(Bb2.y,w3,a1[3][3]);
    }

#pragma unroll
    for (int tt = 0; tt < 2; tt++) {
        int t = t0 + tt;
#pragma unroll
        for (int j = 0; j < 4; j++) {
            int col = c0 + (lane << 2) + j;
            float bj = isIH ? bias[col] : 0.f;
            u64 (*acc)[4] = tt ? a1 : a0;
            float2 p0 = unpack2(acc[j][0]);
            float2 p1 = unpack2(acc[j][1]);
            float2 p2 = unpack2(acc[j][2]);
            float2 p3 = unpack2(acc[j][3]);
            float4 lo = make_float4(p0.x+bj, p0.y+bj, p1.x+bj, p1.y+bj);
            float4 hi = make_float4(p2.x+bj, p2.y+bj, p3.x+bj, p3.y+bj);
            float* dst = (isIH ? g_wiT + ((size_t)t*G3_ + col)*B_
                               : g_xmT + ((size_t)t*H_  + col)*B_) + (warp << 3);
            *(float4*)(dst)     = lo;
            *(float4*)(dst + 4) = hi;
        }
    }
}

// ---------------- persistent recurrence kernel (3 barriers/step) ---------
__global__ void __launch_bounds__(512, 1) k_step(
    const float* __restrict__ W_hm, const float* __restrict__ W_um,
    const float* __restrict__ fc1_w,
    const float* __restrict__ fc2_w, const float* __restrict__ fc2_b,
    const float* __restrict__ W_hh, const float* __restrict__ bias,
    const int* __restrict__ length)
{
    extern __shared__ float smw[];
    __shared__ int sIdx;
    float* sm = smw + SM_RED;
    const int warp = threadIdx.x >> 5, lane = threadIdx.x & 31;
    const int m0 = blockIdx.x << 2;
    const int k0 = warp << 5;
    unsigned bar = 0;

    // ---- stage weight slices into smem (once) ----
    for (int idx = threadIdx.x; idx < 2048; idx += 512) {
        int k = idx >> 2, c = idx & 3;
        smw[SW_HM  + idx] = W_hm [(size_t)k*H_ + m0 + c];
        smw[SW_BOT + idx] = fc2_w[(size_t)(H_ + k)*H_ + m0 + c];
        smw[SW_TOP + idx] = fc2_w[(size_t)k*H_ + m0 + c];
        smw[SW_R   + idx] = W_hh [(size_t)k*G3_ + m0 + c];
        smw[SW_Z   + idx] = W_hh [(size_t)k*G3_ + 512 + m0 + c];
        smw[SW_N   + idx] = W_hh [(size_t)k*G3_ + 1024 + m0 + c];
    }
    for (int idx = threadIdx.x; idx < 256; idx += 512) {
        int n = idx >> 2, c = idx & 3;
        smw[SW_UM + idx] = W_um[(size_t)n*H_ + m0 + c];
    }
    __syncthreads();

    // reducer mapping for phase A (384 threads: sel = pre/bot/top)
    const int asel = threadIdx.x >> 7;
    const int ac   = (threadIdx.x >> 5) & 3;
    const int ab_  = threadIdx.x & 31;
    const int am   = m0 + ac;

    // reducer mapping for phase E (128 threads)
    const int rc = threadIdx.x >> 5;
    const int rb = threadIdx.x & 31;
    const int rm = m0 + rc;
    float biasR = 0.f, biasZ = 0.f, biasN = 0.f; int mylen = 0;
    if (threadIdx.x < 128) {
        biasR = bias[3*H_ + rm];
        biasZ = bias[3*H_ + 512 + rm];
        biasN = bias[3*H_ + 1024 + rm];
        mylen = length[rb];
    }
    const float fc2b_t = fc2_b[threadIdx.x];

    // per-warp smem weight bases
    const float* sWhm = smw + SW_HM  + (k0 << 2);
    const float* sWbo = smw + SW_BOT + (k0 << 2);
    const float* sWto = smw + SW_TOP + (k0 << 2);
    const float* sWr  = smw + SW_R   + (k0 << 2);
    const float* sWz  = smw + SW_Z   + (k0 << 2);
    const float* sWn  = smw + SW_N   + (k0 << 2);

    // prologue prefetch: xm for t=0
    float xm_pf = 0.f;
    if (threadIdx.x < 384 && asel == 0)
        xm_pf = __ldcg(g_xmT + ((size_t)0*H_ + am)*B_ + ab_);

    for (int t = 0; t < T_; t++) {
        // ===== Phase A: fused 3-GEMM on h (+ lu@W_um), weights from smem ====
        {
            int slot_pf = 0;
            if (threadIdx.x < 384 && asel == 2)
                slot_pf = (t < N_) ? t : __ldcg(&g_hard[ab_]);

            float xv[32], lv[4];
            const float* Xp = g_hT + k0*B_ + lane;
#pragma unroll
            for (int k = 0; k < 32; k++) xv[k] = __ldcg(Xp + k*B_);
#pragma unroll
            for (int j = 0; j < 4; j++) lv[j] = __ldcg(g_lu + (warp*4 + j)*B_ + lane);

            u64 P01=0, P23=0, Bo01=0, Bo23=0, To01=0, To23=0;
#pragma unroll
            for (int k = 0; k < 32; k++) {
                u64 x2 = pack2(xv[k]);
                ulonglong2 w0 = *(const ulonglong2*)(sWhm + (k << 2));
                ulonglong2 w1 = *(const ulonglong2*)(sWbo + (k << 2));
                ulonglong2 w2 = *(const ulonglong2*)(sWto + (k << 2));
                P01  = fma2(x2, w0.x, P01);  P23  = fma2(x2, w0.y, P23);
                Bo01 = fma2(x2, w1.x, Bo01); Bo23 = fma2(x2, w1.y, Bo23);
                To01 = fma2(x2, w2.x, To01); To23 = fma2(x2, w2.y, To23);
            }
#pragma unroll
            for (int j = 0; j < 4; j++) {
                u64 l2 = pack2(lv[j]);
                ulonglong2 wu = *(const ulonglong2*)(smw + SW_UM + ((warp*4 + j) << 2));
                P01 = fma2(l2, wu.x, P01); P23 = fma2(l2, wu.y, P23);
            }
            float* s = sm + warp*384;
            float2 f;
            f = unpack2(P01);  s[0*32+lane]=f.x;  s[1*32+lane]=f.y;
            f = unpack2(P23);  s[2*32+lane]=f.x;  s[3*32+lane]=f.y;
            f = unpack2(Bo01); s[4*32+lane]=f.x;  s[5*32+lane]=f.y;
            f = unpack2(Bo23); s[6*32+lane]=f.x;  s[7*32+lane]=f.y;
            f = unpack2(To01); s[8*32+lane]=f.x;  s[9*32+lane]=f.y;
            f = unpack2(To23); s[10*32+lane]=f.x; s[11*32+lane]=f.y;
            __syncthreads();
            if (threadIdx.x < 384) {
                float v = 0.f;
                const int off = (ac + 4*asel)*32 + ab_;
#pragma unroll
                for (int w = 0; w < 16; w++) v += sm[w*384 + off];
                if (asel == 0)      g_pre[am*B_ + ab_] = tanhf(v + xm_pf);
                else if (asel == 1) g_accbot[(size_t)ab_*H_ + am] = v;
                else                g_MF[((size_t)ab_*N_ + slot_pf)*H_ + am] = v;
            }
        }

        // early prefetch (t-indexed, independent of B's output)
        float gv0 = 0.f, gv1 = 0.f;
        if (blockIdx.x < B_ && warp == 0) {
            const float* gp = g_gum + ((size_t)t*B_ + blockIdx.x)*N_;
            gv0 = __ldcg(gp + (lane << 1));
            gv1 = __ldcg(gp + (lane << 1) + 1);
        }
        float ri = 0.f, zi = 0.f, ni = 0.f;
        if (threadIdx.x < 128) {
            const float* wi = g_wiT + (size_t)t*G3_*B_;
            ri = __ldcg(wi + (size_t)rm*B_ + rb);
            zi = __ldcg(wi + (size_t)(512 + rm)*B_ + rb);
            ni = __ldcg(wi + (size_t)(1024 + rm)*B_ + rb);
        }
        grid_bar(++bar);

        // ===== Phase B (blocks 0..31): fc1(f32x2) + argmax + usage/lu + h_new
        if (blockIdx.x < B_) {
            const int b = blockIdx.x;
            const float ab2 = __ldcg(g_accbot + (size_t)b*H_ + threadIdx.x);
            {
                float pv[32];
                const float* Pp = g_pre + k0*B_ + b;
#pragma unroll
                for (int j = 0; j < 32; j++) pv[j] = __ldcg(Pp + j*B_);
                u64 acc = 0ull;
                const float* Fp = fc1_w + (size_t)k0*N_ + (lane << 1);
#pragma unroll
                for (int j = 0; j < 32; j++) {
                    u64 wpair = *(const u64*)(Fp + (size_t)j*N_);
                    acc = fma2(pack2(pv[j]), wpair, acc);
                }
                float2 f = unpack2(acc);
                sm[warp*64 + (lane << 1)]     = f.x;
                sm[warp*64 + (lane << 1) + 1] = f.y;
            }
            __syncthreads();
            if (warp == 0) {
                float v0 = gv0, v1 = gv1;
#pragma unroll
                for (int w = 0; w < 16; w++) {
                    v0 += sm[w*64 + (lane << 1)];
                    v1 += sm[w*64 + (lane << 1) + 1];
                }
                float bv; int bi;
                if (v1 > v0) { bv = v1; bi = (lane << 1) + 1; }
                else         { bv = v0; bi = (lane << 1); }
#pragma unroll
                for (int off = 16; off; off >>= 1) {
                    float ov = __shfl_down_sync(0xffffffffu, bv, off);
                    int   oi = __shfl_down_sync(0xffffffffu, bi, off);
                    if (ov > bv || (ov == bv && oi < bi)) { bv = ov; bi = oi; }
                }
                if (lane == 0) { sIdx = bi; g_hard[b] = bi; }
            }
            __syncthreads();
            const int idx = sIdx;
            if (threadIdx.x < N_) {
                int n = threadIdx.x;
                float u = g_usage[b*N_ + n];
                float un = (n == idx) ? 0.f : (u - 1.f);
                g_usage[b*N_ + n] = un;
                g_lu[n*B_ + b] = 1.f / (1.f + expf(-un));
            }
            {
                int m = threadIdx.x;
                float mf = __ldcg(g_MF + ((size_t)b*N_ + idx)*H_ + m);
                g_hnewT[m*B_ + b] = mf + ab2 + fc2b_t;
            }
        }
        grid_bar(++bar);

        // ===== Phase E: W_hh 3-gate GEMM (smem weights) + gates + store =====
        {
            float xv[32];
            const float* Xp = g_hnewT + k0*B_ + lane;
#pragma unroll
            for (int k = 0; k < 32; k++) xv[k] = __ldcg(Xp + k*B_);

            float hn_pf = 0.f;
            if (threadIdx.x < 128) hn_pf = __ldcg(g_hnewT + rm*B_ + rb);

            u64 R01=0, R23=0, Z01=0, Z23=0, Nn01=0, Nn23=0;
#pragma unroll
            for (int k = 0; k < 32; k++) {
                u64 x2 = pack2(xv[k]);
                ulonglong2 wr = *(const ulonglong2*)(sWr + (k << 2));
                ulonglong2 wz = *(const ulonglong2*)(sWz + (k << 2));
                ulonglong2 wn = *(const ulonglong2*)(sWn + (k << 2));
                R01  = fma2(x2, wr.x, R01);  R23  = fma2(x2, wr.y, R23);
                Z01  = fma2(x2, wz.x, Z01);  Z23  = fma2(x2, wz.y, Z23);
                Nn01 = fma2(x2, wn.x, Nn01); Nn23 = fma2(x2, wn.y, Nn23);
            }
            float* s = sm + warp*384;
            float2 f;
            f = unpack2(R01);  s[0*32+lane]=f.x;  s[1*32+lane]=f.y;
            f = unpack2(R23);  s[2*32+lane]=f.x;  s[3*32+lane]=f.y;
            f = unpack2(Z01);  s[4*32+lane]=f.x;  s[5*32+lane]=f.y;
            f = unpack2(Z23);  s[6*32+lane]=f.x;  s[7*32+lane]=f.y;
            f = unpack2(Nn01); s[8*32+lane]=f.x;  s[9*32+lane]=f.y;
            f = unpack2(Nn23); s[10*32+lane]=f.x; s[11*32+lane]=f.y;
            __syncthreads();
            if (threadIdx.x < 128) {
                float rv=0.f, zv=0.f, nv=0.f;
#pragma unroll
                for (int w = 0; w < 16; w++) {
                    rv += sm[w*384 + (rc    )*32 + rb];
                    zv += sm[w*384 + (rc + 4)*32 + rb];
                    nv += sm[w*384 + (rc + 8)*32 + rb];
                }
                float r = 1.f/(1.f+expf(-(ri + rv + biasR)));
                float z = 1.f/(1.f+expf(-(zi + zv + biasZ)));
                float nn = tanhf(ni + r*(nv + biasN));
                float h1 = (1.f - z)*nn + z*hn_pf;
                float hprev = g_hT[rm*B_ + rb];
                float h2 = (t < mylen) ? h1 : hprev;
                g_hT[rm*B_ + rb] = h2;
                g_hsT[((size_t)t*H_ + rm)*B_ + rb] = h2;
            }
        }
        // prefetch next step's xm (t+1-indexed, independent)
        if (threadIdx.x < 384 && asel == 0 && t + 1 < T_)
            xm_pf = __ldcg(g_xmT + ((size_t)(t+1)*H_ + am)*B_ + ab_);
        grid_bar(++bar);
    }
}

// ---------------- final: out[t][b][a] = hs[t][b]@fc_w + fc_b ----------------
__global__ void k_out(const float* __restrict__ fc_w,
                      const float* __restrict__ fc_b,
                      float* __restrict__ out) {
    int t = blockIdx.x;
    int warp = threadIdx.x >> 5, lane = threadIdx.x & 31;
    int a0 = warp * 2;
    float acc0 = 0.f, acc1 = 0.f;
    const float* Xp = g_hsT + (size_t)t*H_*B_ + lane;
#pragma unroll 4
    for (int k = 0; k < H_; k++) {
        float xv = Xp[k*B_];
        float2 w = *(const float2*)(fc_w + (size_t)k*A_ + a0);
        acc0 = fmaf(xv, w.x, acc0);
        acc1 = fmaf(xv, w.y, acc1);
    }
    float* o = out + ((size_t)t*B_ + lane)*A_;
    o[a0]     = acc0 + fc_b[a0];
    o[a0 + 1] = acc1 + fc_b[a0 + 1];
}

extern "C" void kernel_launch(void* const* d_in, const int* in_sizes, int n_in,
                              void* d_out, int out_size) {
    (void)in_sizes; (void)n_in; (void)out_size;
    const float* x       = (const float*)d_in[0];
    const int*   length  = (const int*)  d_in[1];
    const float* u_noise = (const float*)d_in[2];
    const float* W_ih    = (const float*)d_in[3];
    const float* W_hh    = (const float*)d_in[4];
    const float* bias    = (const float*)d_in[5];
    const float* W_im    = (const float*)d_in[6];
    const float* W_hm    = (const float*)d_in[7];
    const float* W_um    = (const float*)d_in[8];
    const float* fc1_w   = (const float*)d_in[9];
    const float* fc1_b   = (const float*)d_in[10];
    const float* fc2_w   = (const float*)d_in[11];
    const float* fc2_b   = (const float*)d_in[12];
    const float* fc_w    = (const float*)d_in[13];
    const float* fc_b    = (const float*)d_in[14];
    float* out = (float*)d_out;

    cudaFuncSetAttribute(k_step, cudaFuncAttributeMaxDynamicSharedMemorySize,
                         SMEM_BYTES);

    k_init<<<256, 256>>>();
    k_gumbel<<<(T_*B_*N_ + 255)/256, 256>>>(u_noise, fc1_b);
    k_transpose<<<T_, 512>>>(x);
    k_pregemm<<<(T_/2)*16, 128>>>(W_ih, W_im, bias);
    k_step<<<NB_, 512, SMEM_BYTES>>>(W_hm, W_um, fc1_w, fc2_w, fc2_b,
                                     W_hh, bias, length);
    k_out<<<T_, 512>>>(fc_w, fc_b, out);
}

// round 15
// speedup vs baseline: 1.8588x; 1.8588x over previous
#include <cuda_runtime.h>
#include <cuda_bf16.h>
#include <math.h>

#define T_  128
#define B_  32
#define D_  512
#define H_  512
#define N_  64
#define A_  32
#define G3_ 1536
#define NB_ 128

// smem layout (floats) for k_step
#define SW_HM  0
#define SW_BOT 2048
#define SW_TOP 4096
#define SW_UM  6144
#define SW_R   6400
#define SW_Z   8448
#define SW_N   10496
#define SM_RED 12544
#define SMEM_FLOATS (SM_RED + 16*384)
#define SMEM_BYTES  (SMEM_FLOATS * 4)

typedef unsigned long long u64;

// ---------------- device scratch ----------------
__device__ float g_xT  [(size_t)T_*D_*B_];    // [t][k][b]
__device__ float g_wiT [(size_t)T_*G3_*B_];   // x@W_ih + bias_ih, [t][j][b]
__device__ float g_xmT [(size_t)T_*H_*B_];    // x@W_im, [t][m][b]
__device__ float g_gum [(size_t)T_*B_*N_];    // gumbel + fc1_b, [t][b][n]
__device__ float g_hsT [(size_t)T_*H_*B_];    // hs outputs [t][m][b]
__device__ float g_hT     [H_*B_];            // h, [m][b]
__device__ float g_pre    [H_*B_];            // tanh preact, [m][b]
__device__ float g_accbot [B_*H_];            // h@fc2_w[H:], [b][m]
__device__ float g_hnewT  [H_*B_];            // [m][b]
__device__ float g_MF  [(size_t)B_*N_*H_];    // MF[b][n][m] = mem[b,n]@fc2_w[:H]
__device__ float g_usage[B_*N_];
__device__ float g_lu   [N_*B_];              // sigmoid(usage), [n][b]
__device__ int   g_hard [B_];
__device__ unsigned g_cnt;                    // single monotonic barrier counter

// ---------------- f32x2 packed helpers ----------------
__device__ __forceinline__ u64 fma2(u64 a, u64 b, u64 c) {
    u64 d;
    asm("fma.rn.f32x2 %0, %1, %2, %3;" : "=l"(d) : "l"(a), "l"(b), "l"(c));
    return d;
}
__device__ __forceinline__ u64 pack2(float x) {
    u64 d;
    unsigned xi = __float_as_uint(x);
    asm("mov.b64 %0, {%1, %1};" : "=l"(d) : "r"(xi));
    return d;
}
__device__ __forceinline__ float2 unpack2(u64 v) {
    float2 f;
    asm("mov.b64 {%0, %1}, %2;" : "=f"(f.x), "=f"(f.y) : "l"(v));
    return f;
}

// ---------------- accurate fp32 log (immune to --use_fast_math) ----------
__device__ __forceinline__ float acc_logf(float x) {
    int e;
    float m = frexpf(x, &e);                 // m in [0.5,1)
    if (m < 0.70710678f) { m = m + m; e -= 1; }
    float s = (m - 1.0f) / (m + 1.0f);       // |s| <= 0.1716
    float s2 = s * s;
    float p = 2.0f/9.0f;
    p = fmaf(p, s2, 2.0f/7.0f);
    p = fmaf(p, s2, 2.0f/5.0f);
    p = fmaf(p, s2, 2.0f/3.0f);
    p = fmaf(p, s2, 2.0f);
    return fmaf((float)e, 0.6931471805599453f, s * p);
}

// ---------------- grid barrier: single counter, direct poll (R12-proven) --
__device__ __forceinline__ void grid_bar(unsigned target) {
    __syncthreads();
    if (threadIdx.x == 0) {
        asm volatile("red.release.gpu.global.add.u32 [%0], 1;"
                     :: "l"(&g_cnt) : "memory");
        unsigned v;
        do {
            asm volatile("ld.acquire.gpu.global.u32 %0, [%1];"
                         : "=r"(v) : "l"(&g_cnt) : "memory");
        } while (v < target);
    }
    __syncthreads();
}

// ---------------- init (every launch: graph-replay determinism) ----------
__global__ void k_init() {
    size_t i = (size_t)blockIdx.x * blockDim.x + threadIdx.x;
    size_t stride = (size_t)gridDim.x * blockDim.x;
    for (size_t j = i; j < (size_t)B_*N_*H_; j += stride) g_MF[j] = 0.f;
    if (i < (size_t)H_*B_) g_hT[i] = 0.f;
    if (i < (size_t)B_*N_) { g_usage[i] = -99999.f; }
    if (i < (size_t)N_*B_) { g_lu[i] = 0.f; }
    if (i < B_) g_hard[i] = 0;
    if (i == 0) g_cnt = 0u;
}

// ---------------- gumbel precompute: g + fc1_b ----------------
__global__ void k_gumbel(const float* __restrict__ u_noise,
                         const float* __restrict__ fc1_b) {
    int i = blockIdx.x * blockDim.x + threadIdx.x;
    if (i >= T_*B_*N_) return;
    float u = u_noise[i];
    float l1 = acc_logf(1e-20f + u);
    float g = -acc_logf(1e-20f - l1);
    g_gum[i] = g + fc1_b[i & (N_-1)];
}

// ---------------- transpose x[t][b][k] -> g_xT[t][k][b] ----------------
__global__ void k_transpose(const float* __restrict__ x) {
    __shared__ float tile[32][33];
    int t = blockIdx.x;
    int w = threadIdx.x >> 5, lane = threadIdx.x & 31;   // 16 warps
    for (int k0 = 0; k0 < D_; k0 += 32) {
#pragma unroll
        for (int bb = 0; bb < 32; bb += 16) {
            int b = w + bb;
            tile[b][lane] = x[((size_t)(t*B_ + b))*D_ + k0 + lane];
        }
        __syncthreads();
#pragma unroll
        for (int kk = 0; kk < 32; kk += 16) {
            int k = k0 + w + kk;
            g_xT[((size_t)t*D_ + k)*B_ + lane] = tile[lane][w + kk];
        }
        __syncthreads();
    }
}

// ---------------- precompute x@W_ih (+bias_ih) and x@W_im (R12 version) --
__global__ void k_pregemm(const float* __restrict__ W_ih,
                          const float* __restrict__ W_im,
                          const float* __restrict__ bias) {
    const int warp = threadIdx.x >> 5, lane = threadIdx.x & 31;
    const int t = blockIdx.x >> 4, cg = blockIdx.x & 15;
    const bool isIH = (cg < 12);
    const int c0 = (isIH ? cg : cg - 12) << 7;          // 128-column group base
    const int stride = isIH ? G3_ : H_;
    const float* Wp = (isIH ? W_ih : W_im) + c0 + (lane << 2);
    const float* Xp = g_xT + (size_t)t * D_ * B_ + (warp << 3);

    u64 acc[4][4];                                       // [col j][b-pair p]
#pragma unroll
    for (int j = 0; j < 4; j++)
#pragma unroll
        for (int p = 0; p < 4; p++) acc[j][p] = 0ull;

#pragma unroll 8
    for (int k = 0; k < D_; k++) {
        ulonglong2 X1 = *(const ulonglong2*)(Xp + (size_t)k*B_);      // b0..b3
        ulonglong2 X2 = *(const ulonglong2*)(Xp + (size_t)k*B_ + 4);  // b4..b7
        float4 wv = *(const float4*)(Wp + (size_t)k*stride);
        u64 w0 = pack2(wv.x), w1 = pack2(wv.y), w2 = pack2(wv.z), w3 = pack2(wv.w);
        acc[0][0]=fma2(X1.x,w0,acc[0][0]); acc[0][1]=fma2(X1.y,w0,acc[0][1]);
        acc[0][2]=fma2(X2.x,w0,acc[0][2]); acc[0][3]=fma2(X2.y,w0,acc[0][3]);
        acc[1][0]=fma2(X1.x,w1,acc[1][0]); acc[1][1]=fma2(X1.y,w1,acc[1][1]);
        acc[1][2]=fma2(X2.x,w1,acc[1][2]); acc[1][3]=fma2(X2.y,w1,acc[1][3]);
        acc[2][0]=fma2(X1.x,w2,acc[2][0]); acc[2][1]=fma2(X1.y,w2,acc[2][1]);
        acc[2][2]=fma2(X2.x,w2,acc[2][2]); acc[2][3]=fma2(X2.y,w2,acc[2][3]);
        acc[3][0]=fma2(X1.x,w3,acc[3][0]); acc[3][1]=fma2(X1.y,w3,acc[3][1]);
        acc[3][2]=fma2(X2.x,w3,acc[3][2]); acc[3][3]=fma2(X2.y,w3,acc[3][3]);
    }

#pragma unroll
    for (int j = 0; j < 4; j++) {
        int col = c0 + (lane << 2) + j;
        float bj = isIH ? bias[col] : 0.f;
        float2 p0 = unpack2(acc[j][0]);
        float2 p1 = unpack2(acc[j][1]);
        float2 p2 = unpack2(acc[j][2]);
        float2 p3 = unpack2(acc[j][3]);
        float4 lo = make_float4(p0.x+bj, p0.y+bj, p1.x+bj, p1.y+bj);
        float4 hi = make_float4(p2.x+bj, p2.y+bj, p3.x+bj, p3.y+bj);
        float* dst = (isIH ? g_wiT + ((size_t)t*G3_ + col)*B_
                           : g_xmT + ((size_t)t*H_  + col)*B_) + (warp << 3);
        *(float4*)(dst)     = lo;
        *(float4*)(dst + 4) = hi;
    }
}

// ---------------- persistent recurrence kernel (3 barriers/step) ---------
__global__ void __launch_bounds__(512, 1) k_step(
    const float* __restrict__ W_hm, const float* __restrict__ W_um,
    const float* __restrict__ fc1_w,
    const float* __restrict__ fc2_w, const float* __restrict__ fc2_b,
    const float* __restrict__ W_hh, const float* __restrict__ bias,
    const int* __restrict__ length)
{
    extern __shared__ float smw[];
    __shared__ int sIdx;
    float* sm = smw + SM_RED;
    const int warp = threadIdx.x >> 5, lane = threadIdx.x & 31;
    const int m0 = blockIdx.x << 2;
    const int k0 = warp << 5;
    unsigned bar = 0;

    // ---- stage weight slices into smem (once) ----
    for (int idx = threadIdx.x; idx < 2048; idx += 512) {
        int k = idx >> 2, c = idx & 3;
        smw[SW_HM  + idx] = W_hm [(size_t)k*H_ + m0 + c];
        smw[SW_BOT + idx] = fc2_w[(size_t)(H_ + k)*H_ + m0 + c];
        smw[SW_TOP + idx] = fc2_w[(size_t)k*H_ + m0 + c];
        smw[SW_R   + idx] = W_hh [(size_t)k*G3_ + m0 + c];
        smw[SW_Z   + idx] = W_hh [(size_t)k*G3_ + 512 + m0 + c];
        smw[SW_N   + idx] = W_hh [(size_t)k*G3_ + 1024 + m0 + c];
    }
    for (int idx = threadIdx.x; idx < 256; idx += 512) {
        int n = idx >> 2, c = idx & 3;
        smw[SW_UM + idx] = W_um[(size_t)n*H_ + m0 + c];
    }
    __syncthreads();

    // reducer mapping for phase A (384 threads: sel = pre/bot/top)
    const int asel = threadIdx.x >> 7;
    const int ac   = (threadIdx.x >> 5) & 3;
    const int ab_  = threadIdx.x & 31;
    const int am   = m0 + ac;

    // reducer mapping for phase E (128 threads)
    const int rc = threadIdx.x >> 5;
    const int rb = threadIdx.x & 31;
    const int rm = m0 + rc;
    float biasR = 0.f, biasZ = 0.f, biasN = 0.f; int mylen = 0;
    if (threadIdx.x < 128) {
        biasR = bias[3*H_ + rm];
        biasZ = bias[3*H_ + 512 + rm];
        biasN = bias[3*H_ + 1024 + rm];
        mylen = length[rb];
    }
    const float fc2b_t = fc2_b[threadIdx.x];

    // per-warp smem weight bases
    const float* sWhm = smw + SW_HM  + (k0 << 2);
    const float* sWbo = smw + SW_BOT + (k0 << 2);
    const float* sWto = smw + SW_TOP + (k0 << 2);
    const float* sWr  = smw + SW_R   + (k0 << 2);
    const float* sWz  = smw + SW_Z   + (k0 << 2);
    const float* sWn  = smw + SW_N   + (k0 << 2);

    // prologue prefetch: xm for t=0
    float xm_pf = 0.f;
    if (threadIdx.x < 384 && asel == 0)
        xm_pf = __ldcg(g_xmT + ((size_t)0*H_ + am)*B_ + ab_);

    for (int t = 0; t < T_; t++) {
        // ===== Phase A: fused 3-GEMM on h (+ lu@W_um), weights from smem ====
        // Activation loads double-buffered in batches of 8 (MLP burst 32->8,
        // below the cross-CTA L1tex spread threshold) while staying hidden.
        {
            int slot_pf = 0;
            if (threadIdx.x < 384 && asel == 2)
                slot_pf = (t < N_) ? t : __ldcg(&g_hard[ab_]);

            float lv[4];
#pragma unroll
            for (int j = 0; j < 4; j++) lv[j] = __ldcg(g_lu + (warp*4 + j)*B_ + lane);

            const float* Xp = g_hT + k0*B_ + lane;
            float cur[8];
#pragma unroll
            for (int j = 0; j < 8; j++) cur[j] = __ldcg(Xp + j*B_);

            u64 P01=0, P23=0, Bo01=0, Bo23=0, To01=0, To23=0;
#pragma unroll
            for (int kb = 0; kb < 4; kb++) {
                float nxt[8];
                if (kb < 3) {
#pragma unroll
                    for (int j = 0; j < 8; j++)
                        nxt[j] = __ldcg(Xp + ((kb+1)*8 + j)*B_);
                }
#pragma unroll
                for (int j = 0; j < 8; j++) {
                    int k = kb*8 + j;
                    u64 x2 = pack2(cur[j]);
                    ulonglong2 w0 = *(const ulonglong2*)(sWhm + (k << 2));
                    ulonglong2 w1 = *(const ulonglong2*)(sWbo + (k << 2));
                    ulonglong2 w2 = *(const ulonglong2*)(sWto + (k << 2));
                    P01  = fma2(x2, w0.x, P01);  P23  = fma2(x2, w0.y, P23);
                    Bo01 = fma2(x2, w1.x, Bo01); Bo23 = fma2(x2, w1.y, Bo23);
                    To01 = fma2(x2, w2.x, To01); To23 = fma2(x2, w2.y, To23);
                }
                if (kb < 3) {
#pragma unroll
                    for (int j = 0; j < 8; j++) cur[j] = nxt[j];
                }
            }
#pragma unroll
            for (int j = 0; j < 4; j++) {
                u64 l2 = pack2(lv[j]);
                ulonglong2 wu = *(const ulonglong2*)(smw + SW_UM + ((warp*4 + j) << 2));
                P01 = fma2(l2, wu.x, P01); P23 = fma2(l2, wu.y, P23);
            }
            float* s = sm + warp*384;
            float2 f;
            f = unpack2(P01);  s[0*32+lane]=f.x;  s[1*32+lane]=f.y;
            f = unpack2(P23);  s[2*32+lane]=f.x;  s[3*32+lane]=f.y;
            f = unpack2(Bo01); s[4*32+lane]=f.x;  s[5*32+lane]=f.y;
            f = unpack2(Bo23); s[6*32+lane]=f.x;  s[7*32+lane]=f.y;
            f = unpack2(To01); s[8*32+lane]=f.x;  s[9*32+lane]=f.y;
            f = unpack2(To23); s[10*32+lane]=f.x; s[11*32+lane]=f.y;
            __syncthreads();
            if (threadIdx.x < 384) {
                float v = 0.f;
                const int off = (ac + 4*asel)*32 + ab_;
#pragma unroll
                for (int w = 0; w < 16; w++) v += sm[w*384 + off];
                if (asel == 0)      g_pre[am*B_ + ab_] = tanhf(v + xm_pf);
                else if (asel == 1) g_accbot[(size_t)ab_*H_ + am] = v;
                else                g_MF[((size_t)ab_*N_ + slot_pf)*H_ + am] = v;
            }
        }

        // early prefetch (t-indexed, independent of B's output)
        float gv0 = 0.f, gv1 = 0.f;
        if (blockIdx.x < B_ && warp == 0) {
            const float* gp = g_gum + ((size_t)t*B_ + blockIdx.x)*N_;
            gv0 = __ldcg(gp + (lane << 1));
            gv1 = __ldcg(gp + (lane << 1) + 1);
        }
        float ri = 0.f, zi = 0.f, ni = 0.f;
        if (threadIdx.x < 128) {
            const float* wi = g_wiT + (size_t)t*G3_*B_;
            ri = __ldcg(wi + (size_t)rm*B_ + rb);
            zi = __ldcg(wi + (size_t)(512 + rm)*B_ + rb);
            ni = __ldcg(wi + (size_t)(1024 + rm)*B_ + rb);
        }
        grid_bar(++bar * NB_);

        // ===== Phase B (blocks 0..31): fc1(f32x2) + argmax + usage/lu + h_new
        if (blockIdx.x < B_) {
            const int b = blockIdx.x;
            const float ab2 = __ldcg(g_accbot + (size_t)b*H_ + threadIdx.x);
            {
                float pv[32];
                const float* Pp = g_pre + k0*B_ + b;
#pragma unroll
                for (int j = 0; j < 32; j++) pv[j] = __ldcg(Pp + j*B_);
                u64 acc = 0ull;
                const float* Fp = fc1_w + (size_t)k0*N_ + (lane << 1);
#pragma unroll
                for (int j = 0; j < 32; j++) {
                    u64 wpair = *(const u64*)(Fp + (size_t)j*N_);
                    acc = fma2(pack2(pv[j]), wpair, acc);
                }
                float2 f = unpack2(acc);
                sm[warp*64 + (lane << 1)]     = f.x;
                sm[warp*64 + (lane << 1) + 1] = f.y;
            }
            __syncthreads();
            if (warp == 0) {
                float v0 = gv0, v1 = gv1;
#pragma unroll
                for (int w = 0; w < 16; w++) {
                    v0 += sm[w*64 + (lane << 1)];
                    v1 += sm[w*64 + (lane << 1) + 1];
                }
                float bv; int bi;
                if (v1 > v0) { bv = v1; bi = (lane << 1) + 1; }
                else         { bv = v0; bi = (lane << 1); }
#pragma unroll
                for (int off = 16; off; off >>= 1) {
                    float ov = __shfl_down_sync(0xffffffffu, bv, off);
                    int   oi = __shfl_down_sync(0xffffffffu, bi, off);
                    if (ov > bv || (ov == bv && oi < bi)) { bv = ov; bi = oi; }
                }
                if (lane == 0) { sIdx = bi; g_hard[b] = bi; }
            }
            __syncthreads();
            const int idx = sIdx;
            if (threadIdx.x < N_) {
                int n = threadIdx.x;
                float u = g_usage[b*N_ + n];
                float un = (n == idx) ? 0.f : (u - 1.f);
                g_usage[b*N_ + n] = un;
                g_lu[n*B_ + b] = 1.f / (1.f + expf(-un));
            }
            {
                int m = threadIdx.x;
                float mf = __ldcg(g_MF + ((size_t)b*N_ + idx)*H_ + m);
                g_hnewT[m*B_ + b] = mf + ab2 + fc2b_t;
            }
        }
        grid_bar(++bar * NB_);

        // ===== Phase E: W_hh 3-gate GEMM (smem weights) + gates + store =====
        {
            const float* Xp = g_hnewT + k0*B_ + lane;
            float cur[8];
#pragma unroll
            for (int j = 0; j < 8; j++) cur[j] = __ldcg(Xp + j*B_);

            float hn_pf = 0.f;
            if (threadIdx.x < 128) hn_pf = __ldcg(g_hnewT + rm*B_ + rb);

            u64 R01=0, R23=0, Z01=0, Z23=0, Nn01=0, Nn23=0;
#pragma unroll
            for (int kb = 0; kb < 4; kb++) {
                float nxt[8];
                if (kb < 3) {
#pragma unroll
                    for (int j = 0; j < 8; j++)
                        nxt[j] = __ldcg(Xp + ((kb+1)*8 + j)*B_);
                }
#pragma unroll
                for (int j = 0; j < 8; j++) {
                    int k = kb*8 + j;
                    u64 x2 = pack2(cur[j]);
                    ulonglong2 wr = *(const ulonglong2*)(sWr + (k << 2));
                    ulonglong2 wz = *(const ulonglong2*)(sWz + (k << 2));
                    ulonglong2 wn = *(const ulonglong2*)(sWn + (k << 2));
                    R01  = fma2(x2, wr.x, R01);  R23  = fma2(x2, wr.y, R23);
                    Z01  = fma2(x2, wz.x, Z01);  Z23  = fma2(x2, wz.y, Z23);
                    Nn01 = fma2(x2, wn.x, Nn01); Nn23 = fma2(x2, wn.y, Nn23);
                }
                if (kb < 3) {
#pragma unroll
                    for (int j = 0; j < 8; j++) cur[j] = nxt[j];
                }
            }
            float* s = sm + warp*384;
            float2 f;
            f = unpack2(R01);  s[0*32+lane]=f.x;  s[1*32+lane]=f.y;
            f = unpack2(R23);  s[2*32+lane]=f.x;  s[3*32+lane]=f.y;
            f = unpack2(Z01);  s[4*32+lane]=f.x;  s[5*32+lane]=f.y;
            f = unpack2(Z23);  s[6*32+lane]=f.x;  s[7*32+lane]=f.y;
            f = unpack2(Nn01); s[8*32+lane]=f.x;  s[9*32+lane]=f.y;
            f = unpack2(Nn23); s[10*32+lane]=f.x; s[11*32+lane]=f.y;
            __syncthreads();
            if (threadIdx.x < 128) {
                float rv=0.f, zv=0.f, nv=0.f;
#pragma unroll
                for (int w = 0; w < 16; w++) {
                    rv += sm[w*384 + (rc    )*32 + rb];
                    zv += sm[w*384 + (rc + 4)*32 + rb];
                    nv += sm[w*384 + (rc + 8)*32 + rb];
                }
                float r = 1.f/(1.f+expf(-(ri + rv + biasR)));
                float z = 1.f/(1.f+expf(-(zi + zv + biasZ)));
                float nn = tanhf(ni + r*(nv + biasN));
                float h1 = (1.f - z)*nn + z*hn_pf;
                float hprev = g_hT[rm*B_ + rb];
                float h2 = (t < mylen) ? h1 : hprev;
                g_hT[rm*B_ + rb] = h2;
                g_hsT[((size_t)t*H_ + rm)*B_ + rb] = h2;
            }
        }
        // prefetch next step's xm (t+1-indexed, independent)
        if (threadIdx.x < 384 && asel == 0 && t + 1 < T_)
            xm_pf = __ldcg(g_xmT + ((size_t)(t+1)*H_ + am)*B_ + ab_);
        grid_bar(++bar * NB_);
    }
}

// ---------------- final: out[t][b][a] = hs[t][b]@fc_w + fc_b ----------------
__global__ void k_out(const float* __restrict__ fc_w,
                      const float* __restrict__ fc_b,
                      float* __restrict__ out) {
    int t = blockIdx.x;
    int warp = threadIdx.x >> 5, lane = threadIdx.x & 31;
    int a0 = warp * 2;
    float acc0 = 0.f, acc1 = 0.f;
    const float* Xp = g_hsT + (size_t)t*H_*B_ + lane;
#pragma unroll 4
    for (int k = 0; k < H_; k++) {
        float xv = Xp[k*B_];
        float2 w = *(const float2*)(fc_w + (size_t)k*A_ + a0);
        acc0 = fmaf(xv, w.x, acc0);
        acc1 = fmaf(xv, w.y, acc1);
    }
    float* o = out + ((size_t)t*B_ + lane)*A_;
    o[a0]     = acc0 + fc_b[a0];
    o[a0 + 1] = acc1 + fc_b[a0 + 1];
}

extern "C" void kernel_launch(void* const* d_in, const int* in_sizes, int n_in,
                              void* d_out, int out_size) {
    (void)in_sizes; (void)n_in; (void)out_size;
    const float* x       = (const float*)d_in[0];
    const int*   length  = (const int*)  d_in[1];
    const float* u_noise = (const float*)d_in[2];
    const float* W_ih    = (const float*)d_in[3];
    const float* W_hh    = (const float*)d_in[4];
    const float* bias    = (const float*)d_in[5];
    const float* W_im    = (const float*)d_in[6];
    const float* W_hm    = (const float*)d_in[7];
    const float* W_um    = (const float*)d_in[8];
    const float* fc1_w   = (const float*)d_in[9];
    const float* fc1_b   = (const float*)d_in[10];
    const float* fc2_w   = (const float*)d_in[11];
    const float* fc2_b   = (const float*)d_in[12];
    const float* fc_w    = (const float*)d_in[13];
    const float* fc_b    = (const float*)d_in[14];
    float* out = (float*)d_out;

    cudaFuncSetAttribute(k_step, cudaFuncAttributeMaxDynamicSharedMemorySize,
                         SMEM_BYTES);

    k_init<<<256, 256>>>();
    k_gumbel<<<(T_*B_*N_ + 255)/256, 256>>>(u_noise, fc1_b);
    k_transpose<<<T_, 512>>>(x);
    k_pregemm<<<T_*16, 128>>>(W_ih, W_im, bias);
    k_step<<<NB_, 512, SMEM_BYTES>>>(W_hm, W_um, fc1_w, fc2_w, fc2_b,
                                     W_hh, bias, length);
    k_out<<<T_, 512>>>(fc_w, fc_b, out);
}